// round 7
// baseline (speedup 1.0000x reference)
#include <cuda_runtime.h>
#include <math.h>
#include <stdint.h>

// Fixed dataset shapes: N=1024, P=4, G=20000 (tolerates N%32==0, P==4, G<=G_MAX)
#define G_MAX 20480
#define N_MAX 1024
#define CH    512          // genes per pass1 chunk
#define NC_MAX 48          // max gene chunks
#define RP2   8            // rows per pass2 block
#define MAX_B2 4096        // max pass2 blocks

// ---- device scratch (static; no allocations) ----
__device__ __align__(16) float g_r[G_MAX];     // 1/softplus(phi)  (raw)
__device__ __align__(16) float g_C2[G_MAX];    // per-gene const, base-2 units
__device__ __align__(16) float g_mu2[G_MAX];   // mu * log2e
__device__ __align__(16) float g_q0[G_MAX];    // beta row 0 * log2e
__device__ __align__(16) float g_q1[G_MAX];
__device__ __align__(16) float g_q2[G_MAX];
__device__ __align__(16) float g_q3[G_MAX];
__device__ float  g_tab[512];                  // (lgamma(k+1)+k) * log2e
__device__ float  g_Zp[NC_MAX * N_MAX];        // per-(chunk,row) sum exp(lu)
__device__ float  g_Sp[NC_MAX * N_MAX];        // per-(chunk,row) sum Y
__device__ double g_prior[NC_MAX];             // per-chunk prior partial (nats)
__device__ double g_part[MAX_B2];              // per-pass2-block partial (nats)
__device__ unsigned g_ticket;                  // monotone ticket (mod #blocks)

#define NORM_CONST   1.6120857137646180f       // 0.5*log(8*pi), s=2 normal prior
#define HALF_LOG_2PI 0.9189385332046727f
#define LOG2E        1.4426950408889634f
#define LN2          0.6931471805599453
#define SER_K        0.12022458674074694f      // LOG2E / 12
#define SHIFT4       5.7707801635558537f       // 4 * LOG2E

// raw MUFU ops (1 issue slot each)
__device__ __forceinline__ float ex2a(float a){ float r; asm("ex2.approx.ftz.f32 %0,%1;":"=f"(r):"f"(a)); return r; }
__device__ __forceinline__ float lg2a(float a){ float r; asm("lg2.approx.ftz.f32 %0,%1;":"=f"(r):"f"(a)); return r; }
__device__ __forceinline__ float rcpa(float a){ float r; asm("rcp.approx.ftz.f32 %0,%1;":"=f"(r):"f"(a)); return r; }

// ---- block reduce for double (256 threads) ----
__device__ __forceinline__ double blk_reduce256(double v, double* sRed) {
    int t = threadIdx.x, lane = t & 31, wid = t >> 5;
    #pragma unroll
    for (int off = 16; off; off >>= 1)
        v += __shfl_down_sync(0xffffffffu, v, off);
    if (lane == 0) sRed[wid] = v;
    __syncthreads();
    if (t < 8) {
        v = sRed[t];
        #pragma unroll
        for (int off = 4; off; off >>= 1)
            v += __shfl_down_sync(0x000000ffu, v, off);
    }
    return v;  // valid in thread 0
}

// ---- per-element NB log-pmf core, BASE-2 units ----
// b*, mug are pre-scaled by log2e; wn = log2(S/Z); result must be * ln2 later.
__device__ __forceinline__ float nb_elem(float4 xr, float wn, float y,
                                         float b0, float b1, float b2, float b3,
                                         float mug, float r,
                                         const float* __restrict__ sT) {
    float tt = fmaf(xr.x, b0, fmaf(xr.y, b1, fmaf(xr.z, b2, fmaf(xr.w, b3, mug)))) + wn;
    float m  = ex2a(tt);                 // mean (linear)
    float lg = lg2a(r + m);              // log2(r+m)
    float x  = y + r;
    float xs = x, extra = 0.f;
    if (x < 4.f) {                       // shift-by-4 for Stirling validity
        float p = (x * (x + 1.f)) * ((x + 2.f) * (x + 3.f));
        extra = -lg2a(p) - SHIFT4;       // -4*log2e: Stirling's -x uses shifted x
        xs = x + 4.f;
    }
    float z    = rcpa(xs);
    float stir = fmaf(xs - 0.5f, lg2a(xs), fmaf(z, SER_K, extra));
    return stir - sT[(int)y] + fmaf(y, tt, -x * lg);
}

// =========================================================================
// Pass 1: per-(chunk,row) sumexp(lu) and sum(Y); by==0 blocks also do the
// per-gene setup (r, C2, scaled params), priors, and the lgamma table.
// grid (NCHUNK, N/32), 256 threads; warp w owns rows by*32 + 4w .. +3
// =========================================================================
template <bool VEC>
__global__ void __launch_bounds__(256) k_pass1(
        const float* __restrict__ X, const float* __restrict__ Y,
        const float* __restrict__ mu, const float* __restrict__ beta,
        const float* __restrict__ phi, int N, int G) {
    __shared__ float smu[CH], sb0[CH], sb1[CH], sb2[CH], sb3[CH];
    __shared__ double sRed[8];

    int gbase = blockIdx.x * CH;
    int gmax  = min(CH, G - gbase);
    for (int i = threadIdx.x; i < CH; i += 256) {
        int g = gbase + i;
        bool v = (i < gmax);
        smu[i] = v ? __ldg(mu + g)         * LOG2E : -1e30f;
        sb0[i] = v ? __ldg(beta + g)       * LOG2E : 0.f;
        sb1[i] = v ? __ldg(beta + G + g)   * LOG2E : 0.f;
        sb2[i] = v ? __ldg(beta + 2*G + g) * LOG2E : 0.f;
        sb3[i] = v ? __ldg(beta + 3*G + g) * LOG2E : 0.f;
    }
    __syncthreads();

    int w = threadIdx.x >> 5, lane = threadIdx.x & 31;
    int n0 = blockIdx.y * 32 + w * 4;
    const float4* X4 = (const float4*)X;
    float4 xr[4];
    const float* Yr[4];
    #pragma unroll
    for (int r = 0; r < 4; r++) {
        int n = min(n0 + r, N - 1);
        xr[r] = X4[n];
        Yr[r] = Y + (size_t)n * G + gbase;
    }

    float ae[4] = {0.f, 0.f, 0.f, 0.f};
    float ay[4] = {0.f, 0.f, 0.f, 0.f};

    #pragma unroll 2
    for (int it = 0; it < CH / 128; it++) {
        int j  = it * 32 + lane;     // quad index in chunk
        int g4 = j * 4;
        float4 m4 = ((const float4*)smu)[j];
        float4 a0 = ((const float4*)sb0)[j];
        float4 a1 = ((const float4*)sb1)[j];
        float4 a2 = ((const float4*)sb2)[j];
        float4 a3 = ((const float4*)sb3)[j];
        #pragma unroll
        for (int r = 0; r < 4; r++) {
            float4 y;
            if (g4 + 3 < gmax) {
                if (VEC) y = *(const float4*)(Yr[r] + g4);
                else { y.x = Yr[r][g4]; y.y = Yr[r][g4+1];
                       y.z = Yr[r][g4+2]; y.w = Yr[r][g4+3]; }
            } else {
                y.x = (g4+0 < gmax) ? Yr[r][g4+0] : 0.f;
                y.y = (g4+1 < gmax) ? Yr[r][g4+1] : 0.f;
                y.z = (g4+2 < gmax) ? Yr[r][g4+2] : 0.f;
                y.w = (g4+3 < gmax) ? Yr[r][g4+3] : 0.f;
            }
            float l0 = fmaf(xr[r].x, a0.x, fmaf(xr[r].y, a1.x, fmaf(xr[r].z, a2.x, fmaf(xr[r].w, a3.x, m4.x))));
            float l1 = fmaf(xr[r].x, a0.y, fmaf(xr[r].y, a1.y, fmaf(xr[r].z, a2.y, fmaf(xr[r].w, a3.y, m4.y))));
            float l2 = fmaf(xr[r].x, a0.z, fmaf(xr[r].y, a1.z, fmaf(xr[r].z, a2.z, fmaf(xr[r].w, a3.z, m4.z))));
            float l3 = fmaf(xr[r].x, a0.w, fmaf(xr[r].y, a1.w, fmaf(xr[r].z, a2.w, fmaf(xr[r].w, a3.w, m4.w))));
            ae[r] += (ex2a(l0) + ex2a(l1)) + (ex2a(l2) + ex2a(l3));
            ay[r] += (y.x + y.y) + (y.z + y.w);
        }
    }

    #pragma unroll
    for (int r = 0; r < 4; r++) {
        float e = ae[r], s = ay[r];
        #pragma unroll
        for (int off = 16; off; off >>= 1) {
            e += __shfl_down_sync(0xffffffffu, e, off);
            s += __shfl_down_sync(0xffffffffu, s, off);
        }
        if (lane == 0 && n0 + r < N) {
            g_Zp[blockIdx.x * N_MAX + n0 + r] = e;
            g_Sp[blockIdx.x * N_MAX + n0 + r] = s;
        }
    }

    // ---- setup + priors (one row-block per chunk) ----
    if (blockIdx.y == 0) {
        double lp = 0.0;
        for (int i = threadIdx.x; i < gmax; i += 256) {
            int g = gbase + i;
            float ph = __ldg(phi + g);
            float sp = fmaxf(ph, 0.f) + log1pf(expf(-fabsf(ph)));  // softplus
            float r  = 1.f / sp;
            g_r[g]   = r;
            g_C2[g]  = (r * logf(r) - lgammaf(r) - r + HALF_LOG_2PI) * LOG2E;
            g_mu2[g] = smu[i];            // already * log2e
            g_q0[g]  = sb0[i];
            g_q1[g]  = sb1[i];
            g_q2[g]  = sb2[i];
            g_q3[g]  = sb3[i];
            float m  = __ldg(mu + g);
            float b0 = __ldg(beta + g),       b1 = __ldg(beta + G + g);
            float b2 = __ldg(beta + 2*G + g), b3 = __ldg(beta + 3*G + g);
            lp += (double)(logf(sp) - sp - NORM_CONST - 0.125f * m * m);
            lp += (double)(-4.f * NORM_CONST
                           - 0.125f * ((b0*b0 + b1*b1) + (b2*b2 + b3*b3)));
        }
        if (blockIdx.x == 0)
            for (int i = threadIdx.x; i < 512; i += 256)
                g_tab[i] = (lgammaf((float)i + 1.f) + (float)i) * LOG2E;
        __syncthreads();
        double tot = blk_reduce256(lp, sRed);
        if (threadIdx.x == 0) g_prior[blockIdx.x] = tot;
    }
}

// =========================================================================
// Pass 2: main NB likelihood. grid (ceil(G/1024), ceil(N/RP2)), 256 threads.
// Thread owns 4 genes (float4), loops RP2=8 rows; base-2 float accumulation,
// *ln2 once per thread. Last block (ticket) folds partials + priors -> out.
// =========================================================================
template <bool VEC>
__global__ void __launch_bounds__(256, 4) k_pass2(
        const float* __restrict__ X, const float* __restrict__ Y,
        float* __restrict__ out, int N, int G, int NCHUNK, int nblocks) {
    __shared__ float4 sX[RP2];
    __shared__ float  sW[RP2];
    __shared__ float  sT[512];
    __shared__ double sRed[8];
    __shared__ int    sLast;

    int t = threadIdx.x;
    int row0 = blockIdx.y * RP2;
    int rh   = min(RP2, N - row0);
    if (t < RP2) {
        int n = min(row0 + t, N - 1);
        sX[t] = ((const float4*)X)[n];
        float Z = 0.f, S = 0.f;
        for (int c = 0; c < NCHUNK; c++) {
            Z += g_Zp[c * N_MAX + n];
            S += g_Sp[c * N_MAX + n];
        }
        sW[t] = lg2a(S) - lg2a(Z);       // base-2 row offset
    }
    for (int i = t; i < 512; i += 256) sT[i] = g_tab[i];
    __syncthreads();

    int g4 = (blockIdx.x * 256 + t) * 4;
    bool valid = g4 < G;
    float a0 = 0.f, a1 = 0.f, a2 = 0.f, a3 = 0.f;
    double d = 0.0;

    if (valid) {
        bool full = (g4 + 3 < G);
        int gc0 = g4;
        int gc1 = min(g4 + 1, G - 1);
        int gc2 = min(g4 + 2, G - 1);
        int gc3 = min(g4 + 3, G - 1);
        float m0 = g_mu2[gc0], m1 = g_mu2[gc1], m2 = g_mu2[gc2], m3 = g_mu2[gc3];
        float p00 = g_q0[gc0], p01 = g_q0[gc1], p02 = g_q0[gc2], p03 = g_q0[gc3];
        float p10 = g_q1[gc0], p11 = g_q1[gc1], p12 = g_q1[gc2], p13 = g_q1[gc3];
        float p20 = g_q2[gc0], p21 = g_q2[gc1], p22 = g_q2[gc2], p23 = g_q2[gc3];
        float p30 = g_q3[gc0], p31 = g_q3[gc1], p32 = g_q3[gc2], p33 = g_q3[gc3];
        float r0 = g_r[gc0], r1 = g_r[gc1], r2 = g_r[gc2], r3 = g_r[gc3];

        // fold per-gene constants up front (base-2 units)
        {
            float csum = g_C2[gc0];
            if (g4 + 1 < G) csum += g_C2[gc1];
            if (g4 + 2 < G) csum += g_C2[gc2];
            if (g4 + 3 < G) csum += g_C2[gc3];
            d = (double)rh * (double)csum;
        }

        if (full && VEC && rh == RP2) {
            const float* Yp = Y + (size_t)row0 * G + g4;
            #pragma unroll
            for (int i = 0; i < RP2; i++) {
                float4 y = *(const float4*)Yp;
                Yp += G;
                float4 xr = sX[i];
                float  wn = sW[i];
                a0 += nb_elem(xr, wn, y.x, p00, p10, p20, p30, m0, r0, sT);
                a1 += nb_elem(xr, wn, y.y, p01, p11, p21, p31, m1, r1, sT);
                a2 += nb_elem(xr, wn, y.z, p02, p12, p22, p32, m2, r2, sT);
                a3 += nb_elem(xr, wn, y.w, p03, p13, p23, p33, m3, r3, sT);
            }
        } else {
            for (int i = 0; i < rh; i++) {
                const float* Yp = Y + (size_t)(row0 + i) * G;
                float4 y;
                y.x = Yp[gc0]; y.y = Yp[gc1]; y.z = Yp[gc2]; y.w = Yp[gc3];
                float4 xr = sX[i];
                float  wn = sW[i];
                a0 += nb_elem(xr, wn, y.x, p00, p10, p20, p30, m0, r0, sT);
                a1 += nb_elem(xr, wn, y.y, p01, p11, p21, p31, m1, r1, sT);
                a2 += nb_elem(xr, wn, y.z, p02, p12, p22, p32, m2, r2, sT);
                a3 += nb_elem(xr, wn, y.w, p03, p13, p23, p33, m3, r3, sT);
            }
        }
        d += (double)a0;
        if (g4 + 1 < G) d += (double)a1;
        if (g4 + 2 < G) d += (double)a2;
        if (g4 + 3 < G) d += (double)a3;
        d *= LN2;                         // back to nats
    }

    double bsum = blk_reduce256(d, sRed);
    int bid = blockIdx.y * gridDim.x + blockIdx.x;
    if (t == 0) {
        g_part[bid] = bsum;
        __threadfence();
        unsigned old = atomicAdd(&g_ticket, 1u);
        sLast = ((old % (unsigned)nblocks) == (unsigned)(nblocks - 1));
    }
    __syncthreads();

    if (sLast) {
        double s = 0.0;
        for (int i = t; i < nblocks; i += 256) s += g_part[i];
        for (int c = t; c < NCHUNK; c += 256) s += g_prior[c];
        __syncthreads();
        double tot = blk_reduce256(s, sRed);
        if (t == 0) out[0] = (float)tot;
    }
}

extern "C" void kernel_launch(void* const* d_in, const int* in_sizes, int n_in,
                              void* d_out, int out_size) {
    const float* X    = (const float*)d_in[0];
    const float* Y    = (const float*)d_in[1];
    const float* mu   = (const float*)d_in[2];
    const float* beta = (const float*)d_in[3];
    const float* phi  = (const float*)d_in[4];
    float* out = (float*)d_out;

    int G = in_sizes[2];          // 20000
    int N = in_sizes[1] / G;      // 1024

    int NCHUNK = (G + CH - 1) / CH;
    bool vec = ((G & 3) == 0) && ((((unsigned long long)Y) & 15ull) == 0ull);

    dim3 g1(NCHUNK, (N + 31) / 32);
    if (vec) k_pass1<true><<<g1, 256>>>(X, Y, mu, beta, phi, N, G);
    else     k_pass1<false><<<g1, 256>>>(X, Y, mu, beta, phi, N, G);

    int gx2 = (G + 1023) / 1024;
    int gy2 = (N + RP2 - 1) / RP2;
    int nb  = gx2 * gy2;          // 20*128 = 2560 <= MAX_B2
    dim3 g2(gx2, gy2);
    if (vec) k_pass2<true><<<g2, 256>>>(X, Y, out, N, G, NCHUNK, nb);
    else     k_pass2<false><<<g2, 256>>>(X, Y, out, N, G, NCHUNK, nb);
}

// round 8
// speedup vs baseline: 1.0743x; 1.0743x over previous
#include <cuda_runtime.h>
#include <math.h>
#include <stdint.h>

// Fixed dataset shapes: N=1024, P=4, G=20000 (tolerates N%32==0, P==4, G<=G_MAX)
#define G_MAX 20480
#define N_MAX 1024
#define CH    512          // genes per pass1 chunk
#define NC_MAX 48          // max gene chunks
#define RP2   16           // rows per pass2 block
#define MAX_B2 8192        // max pass2 blocks

// ---- device scratch (static; no allocations) ----
__device__ __align__(16) float g_r[G_MAX];     // 1/softplus(phi)  (raw)
__device__ __align__(16) float g_C2[G_MAX];    // per-gene const, base-2 units
__device__ __align__(16) float g_mu2[G_MAX];   // mu * log2e
__device__ __align__(16) float g_q0[G_MAX];    // beta row 0 * log2e
__device__ __align__(16) float g_q1[G_MAX];
__device__ __align__(16) float g_q2[G_MAX];
__device__ __align__(16) float g_q3[G_MAX];
__device__ float  g_tab[512];                  // (lgamma(k+1)+k) * log2e
__device__ float  g_Zp[NC_MAX * N_MAX];        // per-(chunk,row) sum exp(lu)
__device__ float  g_Sp[NC_MAX * N_MAX];        // per-(chunk,row) sum Y
__device__ double g_prior[NC_MAX];             // per-chunk prior partial (nats)
__device__ double g_part[MAX_B2];              // per-pass2-block partial (nats)
__device__ unsigned g_ticket;                  // monotone ticket (mod #blocks)

#define NORM_CONST   1.6120857137646180f       // 0.5*log(8*pi), s=2 normal prior
#define HALF_LOG_2PI 0.9189385332046727f
#define LOG2E        1.4426950408889634f
#define LN2          0.6931471805599453
#define SER_K        0.12022458674074694f      // LOG2E / 12
#define SHIFT4       5.7707801635558537f       // 4 * LOG2E

// raw MUFU ops (1 issue slot each)
__device__ __forceinline__ float ex2a(float a){ float r; asm("ex2.approx.ftz.f32 %0,%1;":"=f"(r):"f"(a)); return r; }
__device__ __forceinline__ float lg2a(float a){ float r; asm("lg2.approx.ftz.f32 %0,%1;":"=f"(r):"f"(a)); return r; }
__device__ __forceinline__ float rcpa(float a){ float r; asm("rcp.approx.ftz.f32 %0,%1;":"=f"(r):"f"(a)); return r; }

// ---- block reduce for double (256 threads) ----
__device__ __forceinline__ double blk_reduce256(double v, double* sRed) {
    int t = threadIdx.x, lane = t & 31, wid = t >> 5;
    #pragma unroll
    for (int off = 16; off; off >>= 1)
        v += __shfl_down_sync(0xffffffffu, v, off);
    if (lane == 0) sRed[wid] = v;
    __syncthreads();
    if (t < 8) {
        v = sRed[t];
        #pragma unroll
        for (int off = 4; off; off >>= 1)
            v += __shfl_down_sync(0x000000ffu, v, off);
    }
    return v;  // valid in thread 0
}

// ---- per-element NB log-pmf core, BASE-2 units, BRANCHLESS ----
// b*, mug pre-scaled by log2e; wn = log2(S/Z); result must be * ln2 later.
__device__ __forceinline__ float nb_elem(float4 xr, float wn, float y,
                                         float b0, float b1, float b2, float b3,
                                         float mug, float r,
                                         const float* __restrict__ sT) {
    float tt = fmaf(xr.x, b0, fmaf(xr.y, b1, fmaf(xr.z, b2, fmaf(xr.w, b3, mug)))) + wn;
    float m  = ex2a(tt);                 // mean (linear)
    float lg = lg2a(r + m);              // log2(r+m)
    float x  = y + r;
    // branchless Stirling shift-by-4 (predicated selects, no BSSY/BSYNC)
    float p  = (x * (x + 1.f)) * ((x + 2.f) * (x + 3.f));
    float lp = lg2a(p);
    bool  sm = x < 4.f;
    float xs    = sm ? x + 4.f : x;
    float extra = sm ? (-lp - SHIFT4) : 0.f;
    float z    = rcpa(xs);
    float stir = fmaf(xs - 0.5f, lg2a(xs), fmaf(z, SER_K, extra));
    return stir - sT[(int)y] + fmaf(y, tt, -x * lg);
}

// =========================================================================
// Pass 1: per-(chunk,row) sumexp(lu) and sum(Y); by==0 blocks also do the
// per-gene setup (r, C2, scaled params), priors, and the lgamma table.
// grid (NCHUNK, N/32), 256 threads; warp w owns rows by*32 + 4w .. +3
// =========================================================================
template <bool VEC>
__global__ void __launch_bounds__(256) k_pass1(
        const float* __restrict__ X, const float* __restrict__ Y,
        const float* __restrict__ mu, const float* __restrict__ beta,
        const float* __restrict__ phi, int N, int G) {
    __shared__ float smu[CH], sb0[CH], sb1[CH], sb2[CH], sb3[CH];
    __shared__ double sRed[8];

    int gbase = blockIdx.x * CH;
    int gmax  = min(CH, G - gbase);
    for (int i = threadIdx.x; i < CH; i += 256) {
        int g = gbase + i;
        bool v = (i < gmax);
        smu[i] = v ? __ldg(mu + g)         * LOG2E : -1e30f;
        sb0[i] = v ? __ldg(beta + g)       * LOG2E : 0.f;
        sb1[i] = v ? __ldg(beta + G + g)   * LOG2E : 0.f;
        sb2[i] = v ? __ldg(beta + 2*G + g) * LOG2E : 0.f;
        sb3[i] = v ? __ldg(beta + 3*G + g) * LOG2E : 0.f;
    }
    __syncthreads();

    int w = threadIdx.x >> 5, lane = threadIdx.x & 31;
    int n0 = blockIdx.y * 32 + w * 4;
    const float4* X4 = (const float4*)X;
    float4 xr[4];
    const float* Yr[4];
    #pragma unroll
    for (int r = 0; r < 4; r++) {
        int n = min(n0 + r, N - 1);
        xr[r] = X4[n];
        Yr[r] = Y + (size_t)n * G + gbase;
    }

    float ae[4] = {0.f, 0.f, 0.f, 0.f};
    float ay[4] = {0.f, 0.f, 0.f, 0.f};

    #pragma unroll 2
    for (int it = 0; it < CH / 128; it++) {
        int j  = it * 32 + lane;     // quad index in chunk
        int g4 = j * 4;
        float4 m4 = ((const float4*)smu)[j];
        float4 a0 = ((const float4*)sb0)[j];
        float4 a1 = ((const float4*)sb1)[j];
        float4 a2 = ((const float4*)sb2)[j];
        float4 a3 = ((const float4*)sb3)[j];
        #pragma unroll
        for (int r = 0; r < 4; r++) {
            float4 y;
            if (g4 + 3 < gmax) {
                if (VEC) y = *(const float4*)(Yr[r] + g4);
                else { y.x = Yr[r][g4]; y.y = Yr[r][g4+1];
                       y.z = Yr[r][g4+2]; y.w = Yr[r][g4+3]; }
            } else {
                y.x = (g4+0 < gmax) ? Yr[r][g4+0] : 0.f;
                y.y = (g4+1 < gmax) ? Yr[r][g4+1] : 0.f;
                y.z = (g4+2 < gmax) ? Yr[r][g4+2] : 0.f;
                y.w = (g4+3 < gmax) ? Yr[r][g4+3] : 0.f;
            }
            float l0 = fmaf(xr[r].x, a0.x, fmaf(xr[r].y, a1.x, fmaf(xr[r].z, a2.x, fmaf(xr[r].w, a3.x, m4.x))));
            float l1 = fmaf(xr[r].x, a0.y, fmaf(xr[r].y, a1.y, fmaf(xr[r].z, a2.y, fmaf(xr[r].w, a3.y, m4.y))));
            float l2 = fmaf(xr[r].x, a0.z, fmaf(xr[r].y, a1.z, fmaf(xr[r].z, a2.z, fmaf(xr[r].w, a3.z, m4.z))));
            float l3 = fmaf(xr[r].x, a0.w, fmaf(xr[r].y, a1.w, fmaf(xr[r].z, a2.w, fmaf(xr[r].w, a3.w, m4.w))));
            ae[r] += (ex2a(l0) + ex2a(l1)) + (ex2a(l2) + ex2a(l3));
            ay[r] += (y.x + y.y) + (y.z + y.w);
        }
    }

    #pragma unroll
    for (int r = 0; r < 4; r++) {
        float e = ae[r], s = ay[r];
        #pragma unroll
        for (int off = 16; off; off >>= 1) {
            e += __shfl_down_sync(0xffffffffu, e, off);
            s += __shfl_down_sync(0xffffffffu, s, off);
        }
        if (lane == 0 && n0 + r < N) {
            g_Zp[blockIdx.x * N_MAX + n0 + r] = e;
            g_Sp[blockIdx.x * N_MAX + n0 + r] = s;
        }
    }

    // ---- setup + priors (one row-block per chunk) ----
    if (blockIdx.y == 0) {
        double lp = 0.0;
        for (int i = threadIdx.x; i < gmax; i += 256) {
            int g = gbase + i;
            float ph = __ldg(phi + g);
            float sp = fmaxf(ph, 0.f) + log1pf(expf(-fabsf(ph)));  // softplus
            float r  = 1.f / sp;
            g_r[g]   = r;
            g_C2[g]  = (r * logf(r) - lgammaf(r) - r + HALF_LOG_2PI) * LOG2E;
            g_mu2[g] = smu[i];            // already * log2e
            g_q0[g]  = sb0[i];
            g_q1[g]  = sb1[i];
            g_q2[g]  = sb2[i];
            g_q3[g]  = sb3[i];
            float m  = __ldg(mu + g);
            float b0 = __ldg(beta + g),       b1 = __ldg(beta + G + g);
            float b2 = __ldg(beta + 2*G + g), b3 = __ldg(beta + 3*G + g);
            lp += (double)(logf(sp) - sp - NORM_CONST - 0.125f * m * m);
            lp += (double)(-4.f * NORM_CONST
                           - 0.125f * ((b0*b0 + b1*b1) + (b2*b2 + b3*b3)));
        }
        if (blockIdx.x == 0)
            for (int i = threadIdx.x; i < 512; i += 256)
                g_tab[i] = (lgammaf((float)i + 1.f) + (float)i) * LOG2E;
        __syncthreads();
        double tot = blk_reduce256(lp, sRed);
        if (threadIdx.x == 0) g_prior[blockIdx.x] = tot;
    }
}

// =========================================================================
// Pass 2: main NB likelihood. grid (ceil(G/512), ceil(N/RP2)), 256 threads.
// Thread owns 2 genes (float2), loops RP2=16 rows; base-2 float accumulation,
// *ln2 once per thread. Last block (ticket) folds partials + priors -> out.
// 2 genes/thread keeps regs low -> 6 blocks/SM -> ~75% occupancy.
// =========================================================================
template <bool VEC>
__global__ void __launch_bounds__(256, 6) k_pass2(
        const float* __restrict__ X, const float* __restrict__ Y,
        float* __restrict__ out, int N, int G, int NCHUNK, int nblocks) {
    __shared__ float4 sX[RP2];
    __shared__ float  sW[RP2];
    __shared__ float  sT[512];
    __shared__ double sRed[8];
    __shared__ int    sLast;

    int t = threadIdx.x;
    int row0 = blockIdx.y * RP2;
    int rh   = min(RP2, N - row0);
    if (t < RP2) {
        int n = min(row0 + t, N - 1);
        sX[t] = ((const float4*)X)[n];
        float Z = 0.f, S = 0.f;
        for (int c = 0; c < NCHUNK; c++) {
            Z += g_Zp[c * N_MAX + n];
            S += g_Sp[c * N_MAX + n];
        }
        sW[t] = lg2a(S) - lg2a(Z);       // base-2 row offset
    }
    for (int i = t; i < 512; i += 256) sT[i] = g_tab[i];
    __syncthreads();

    int gp = (blockIdx.x * 256 + t) * 2;
    bool valid = gp < G;
    float a0 = 0.f, a1 = 0.f;
    double d = 0.0;

    if (valid) {
        bool full = (gp + 1 < G);
        int gc0 = gp;
        int gc1 = min(gp + 1, G - 1);
        float m0 = g_mu2[gc0], m1 = g_mu2[gc1];
        float p00 = g_q0[gc0], p01 = g_q0[gc1];
        float p10 = g_q1[gc0], p11 = g_q1[gc1];
        float p20 = g_q2[gc0], p21 = g_q2[gc1];
        float p30 = g_q3[gc0], p31 = g_q3[gc1];
        float r0 = g_r[gc0], r1 = g_r[gc1];

        // fold per-gene constants up front (base-2 units)
        {
            float csum = g_C2[gc0];
            if (full) csum += g_C2[gc1];
            d = (double)rh * (double)csum;
        }

        if (full && VEC && rh == RP2) {
            const float* Yp = Y + (size_t)row0 * G + gp;
            #pragma unroll 4
            for (int i = 0; i < RP2; i++) {
                float2 y = *(const float2*)Yp;
                Yp += G;
                float4 xr = sX[i];
                float  wn = sW[i];
                a0 += nb_elem(xr, wn, y.x, p00, p10, p20, p30, m0, r0, sT);
                a1 += nb_elem(xr, wn, y.y, p01, p11, p21, p31, m1, r1, sT);
            }
        } else {
            for (int i = 0; i < rh; i++) {
                const float* Yp = Y + (size_t)(row0 + i) * G;
                float yx = Yp[gc0];
                float yy = Yp[gc1];
                float4 xr = sX[i];
                float  wn = sW[i];
                a0 += nb_elem(xr, wn, yx, p00, p10, p20, p30, m0, r0, sT);
                a1 += nb_elem(xr, wn, yy, p01, p11, p21, p31, m1, r1, sT);
            }
        }
        d += (double)a0;
        if (full) d += (double)a1;
        d *= LN2;                         // back to nats
    }

    double bsum = blk_reduce256(d, sRed);
    int bid = blockIdx.y * gridDim.x + blockIdx.x;
    if (t == 0) {
        g_part[bid] = bsum;
        __threadfence();
        unsigned old = atomicAdd(&g_ticket, 1u);
        sLast = ((old % (unsigned)nblocks) == (unsigned)(nblocks - 1));
    }
    __syncthreads();

    if (sLast) {
        double s = 0.0;
        for (int i = t; i < nblocks; i += 256) s += g_part[i];
        for (int c = t; c < NCHUNK; c += 256) s += g_prior[c];
        __syncthreads();
        double tot = blk_reduce256(s, sRed);
        if (t == 0) out[0] = (float)tot;
    }
}

extern "C" void kernel_launch(void* const* d_in, const int* in_sizes, int n_in,
                              void* d_out, int out_size) {
    const float* X    = (const float*)d_in[0];
    const float* Y    = (const float*)d_in[1];
    const float* mu   = (const float*)d_in[2];
    const float* beta = (const float*)d_in[3];
    const float* phi  = (const float*)d_in[4];
    float* out = (float*)d_out;

    int G = in_sizes[2];          // 20000
    int N = in_sizes[1] / G;      // 1024

    int NCHUNK = (G + CH - 1) / CH;
    bool vec = ((G & 1) == 0) && ((((unsigned long long)Y) & 15ull) == 0ull);

    dim3 g1(NCHUNK, (N + 31) / 32);
    if (vec) k_pass1<true><<<g1, 256>>>(X, Y, mu, beta, phi, N, G);
    else     k_pass1<false><<<g1, 256>>>(X, Y, mu, beta, phi, N, G);

    int gx2 = (G + 511) / 512;
    int gy2 = (N + RP2 - 1) / RP2;
    int nb  = gx2 * gy2;          // 40*64 = 2560 <= MAX_B2
    dim3 g2(gx2, gy2);
    if (vec) k_pass2<true><<<g2, 256>>>(X, Y, out, N, G, NCHUNK, nb);
    else     k_pass2<false><<<g2, 256>>>(X, Y, out, N, G, NCHUNK, nb);
}